// round 1
// baseline (speedup 1.0000x reference)
#include <cuda_runtime.h>
#include <cuda_bf16.h>
#include <math.h>

// ---------------------------------------------------------------------------
// GAT encoder: conv1 (H=2, C=128, concat) -> ELU -> {conv_mu, conv_ls} (C=64)
// fused as a 2-head conv sharing one softmax pipeline.
// ---------------------------------------------------------------------------

#define MAX_N 50000
#define MAX_E 400000
#define MAX_ETOT (MAX_N + MAX_E)
#define NEG_SLOPE 0.2f

// scratch (device globals: allocation-free)
__device__ float    g_h1[MAX_N * 256];    // conv1 features h = x@W1  [N,2,128]
__device__ float    g_hact[MAX_N * 256];  // conv1 agg -> ELU output  [N,256]
__device__ float    g_h2[MAX_N * 128];    // layer2 features [N, {mu,ls}, 64]
__device__ float    g_asrc[MAX_N * 2];
__device__ float    g_adst[MAX_N * 2];
__device__ unsigned g_m[MAX_N * 2];
__device__ float    g_den[MAX_N * 2];

// monotonic float<->uint encoding for atomicMax on floats
__device__ __forceinline__ unsigned fenc(float f) {
    unsigned u = __float_as_uint(f);
    return (u >> 31) ? ~u : (u | 0x80000000u);
}
__device__ __forceinline__ float fdec(unsigned u) {
    return __uint_as_float((u >> 31) ? (u & 0x7FFFFFFFu) : ~u);
}
#define ENC_NEG_INF 0x007FFFFFu   // fenc(-inf)

// ---------------------------------------------------------------------------
// SGEMM: C[M,ldc] (+coff) = A[M,K] @ B[K,ldb] (cols [col0..col0+BN))
// BM=128 BN=64 BK=16, 256 threads, 8x4 microtile
// ---------------------------------------------------------------------------
#define BM 128
#define BN 64
#define BK 16
#define TM 8
#define TN 4

__global__ __launch_bounds__(256) void sgemm_k(
    const float* __restrict__ A, const float* __restrict__ B,
    float* __restrict__ C, int M, int K, int ldb, int ldc, int coff)
{
    __shared__ float As[BK][BM];
    __shared__ float Bs[BK][BN];
    const int row0 = blockIdx.y * BM;
    const int col0 = blockIdx.x * BN;
    const int tid = threadIdx.x;
    const int tr = tid / (BN / TN);  // 0..15
    const int tc = tid % (BN / TN);  // 0..15

    float acc[TM][TN];
#pragma unroll
    for (int i = 0; i < TM; i++)
#pragma unroll
        for (int j = 0; j < TN; j++) acc[i][j] = 0.f;

    for (int k0 = 0; k0 < K; k0 += BK) {
#pragma unroll
        for (int i = 0; i < (BM * BK) / 256; i++) {
            int idx = tid + i * 256;
            int m = idx / BK, k = idx % BK;
            int gr = row0 + m;
            As[k][m] = (gr < M) ? A[(size_t)gr * K + k0 + k] : 0.f;
        }
#pragma unroll
        for (int i = 0; i < (BK * BN) / 256; i++) {
            int idx = tid + i * 256;
            int k = idx / BN, c = idx % BN;
            Bs[k][c] = B[(size_t)(k0 + k) * ldb + col0 + c];
        }
        __syncthreads();
#pragma unroll
        for (int k = 0; k < BK; k++) {
            float ra[TM], rb[TN];
#pragma unroll
            for (int i = 0; i < TM; i++) ra[i] = As[k][tr * TM + i];
#pragma unroll
            for (int j = 0; j < TN; j++) rb[j] = Bs[k][tc * TN + j];
#pragma unroll
            for (int i = 0; i < TM; i++)
#pragma unroll
                for (int j = 0; j < TN; j++) acc[i][j] += ra[i] * rb[j];
        }
        __syncthreads();
    }

#pragma unroll
    for (int i = 0; i < TM; i++) {
        int gr = row0 + tr * TM + i;
        if (gr < M) {
#pragma unroll
            for (int j = 0; j < TN; j++)
                C[(size_t)gr * ldc + coff + col0 + tc * TN + j] = acc[i][j];
        }
    }
}

// ---------------------------------------------------------------------------
// attention scalars
// ---------------------------------------------------------------------------
__global__ void att1_kernel(const float* __restrict__ h,
                            const float* __restrict__ att_src,
                            const float* __restrict__ att_dst,
                            float* __restrict__ asrc, float* __restrict__ adst,
                            int Nn)
{
    int i = blockIdx.x * blockDim.x + threadIdx.x;
    if (i >= Nn * 2) return;
    int n = i >> 1, hh = i & 1;
    const float* row = h + (size_t)n * 256 + hh * 128;
    const float* as = att_src + hh * 128;
    const float* ad = att_dst + hh * 128;
    float s = 0.f, d = 0.f;
#pragma unroll 8
    for (int c = 0; c < 128; c++) {
        float v = row[c];
        s += v * as[c];
        d += v * ad[c];
    }
    asrc[i] = s;
    adst[i] = d;
}

__global__ void att2_kernel(const float* __restrict__ h2,
                            const float* __restrict__ as_mu,
                            const float* __restrict__ ad_mu,
                            const float* __restrict__ as_ls,
                            const float* __restrict__ ad_ls,
                            float* __restrict__ asrc, float* __restrict__ adst,
                            int Nn)
{
    int i = blockIdx.x * blockDim.x + threadIdx.x;
    if (i >= Nn * 2) return;
    int n = i >> 1, hh = i & 1;
    const float* row = h2 + (size_t)n * 128 + hh * 64;
    const float* as = hh ? as_ls : as_mu;
    const float* ad = hh ? ad_ls : ad_mu;
    float s = 0.f, d = 0.f;
#pragma unroll 8
    for (int c = 0; c < 64; c++) {
        float v = row[c];
        s += v * as[c];
        d += v * ad[c];
    }
    asrc[i] = s;
    adst[i] = d;
}

// ---------------------------------------------------------------------------
// init kernels
// ---------------------------------------------------------------------------
__global__ void init_softmax_kernel(unsigned* __restrict__ m, float* __restrict__ den, int n)
{
    int i = blockIdx.x * blockDim.x + threadIdx.x;
    if (i < n) { m[i] = ENC_NEG_INF; den[i] = 0.f; }
}

__global__ void init_bias1_kernel(float* __restrict__ out, const float* __restrict__ b, int total)
{
    int i = blockIdx.x * blockDim.x + threadIdx.x;
    if (i < total) out[i] = b[i & 255];
}

__global__ void init_bias2_kernel(float* __restrict__ out, const float* __restrict__ b_mu,
                                  const float* __restrict__ b_ls, int Nn)
{
    int i = blockIdx.x * blockDim.x + threadIdx.x;
    int total = Nn * 128;
    if (i >= total) return;
    int h = i / (Nn * 64);
    int c = i & 63;
    out[i] = h ? b_ls[c] : b_mu[c];
}

// ---------------------------------------------------------------------------
// edge passes (H = 2 hardcoded)
// ---------------------------------------------------------------------------
__device__ __forceinline__ void edge_sd(const int* __restrict__ ei, int nE, int e, int& s, int& d)
{
    if (e < nE) { s = ei[e]; d = ei[nE + e]; }
    else        { s = e - nE; d = s; }
}

__global__ void edge_max_kernel(const int* __restrict__ ei, int nE, int nTot,
                                const float* __restrict__ asrc, const float* __restrict__ adst,
                                unsigned* __restrict__ m)
{
    int t = blockIdx.x * blockDim.x + threadIdx.x;
    if (t >= nTot * 2) return;
    int e = t >> 1, h = t & 1;
    int s, d; edge_sd(ei, nE, e, s, d);
    float v = asrc[s * 2 + h] + adst[d * 2 + h];
    v = v > 0.f ? v : NEG_SLOPE * v;
    atomicMax(&m[d * 2 + h], fenc(v));
}

__global__ void edge_sum_kernel(const int* __restrict__ ei, int nE, int nTot,
                                const float* __restrict__ asrc, const float* __restrict__ adst,
                                const unsigned* __restrict__ m, float* __restrict__ den)
{
    int t = blockIdx.x * blockDim.x + threadIdx.x;
    if (t >= nTot * 2) return;
    int e = t >> 1, h = t & 1;
    int s, d; edge_sd(ei, nE, e, s, d);
    float v = asrc[s * 2 + h] + adst[d * 2 + h];
    v = v > 0.f ? v : NEG_SLOPE * v;
    float w = __expf(v - fdec(m[d * 2 + h]));
    atomicAdd(&den[d * 2 + h], w);
}

// one warp per (edge, head); lanes cover C/4 float4 chunks
template <int C>
__global__ void edge_agg_kernel(const int* __restrict__ ei, int nE, int nTot,
                                const float* __restrict__ asrc, const float* __restrict__ adst,
                                const unsigned* __restrict__ m, const float* __restrict__ den,
                                const float* __restrict__ feat, float* __restrict__ out,
                                long nodeStride, long headStride)
{
    int warp = (blockIdx.x * blockDim.x + threadIdx.x) >> 5;
    int lane = threadIdx.x & 31;
    if (warp >= nTot * 2) return;
    int e = warp >> 1, h = warp & 1;
    int s, d; edge_sd(ei, nE, e, s, d);
    float v = asrc[s * 2 + h] + adst[d * 2 + h];
    v = v > 0.f ? v : NEG_SLOPE * v;
    float alpha = __expf(v - fdec(m[d * 2 + h])) / (den[d * 2 + h] + 1e-16f);

    constexpr int NV = C / 4;
    if (lane < NV) {
        const float4* fp = (const float4*)(feat + (size_t)s * 2 * C + h * C) + lane;
        float4 f = *fp;
        float* op = out + (size_t)d * nodeStride + (size_t)h * headStride + lane * 4;
        atomicAdd(op + 0, alpha * f.x);
        atomicAdd(op + 1, alpha * f.y);
        atomicAdd(op + 2, alpha * f.z);
        atomicAdd(op + 3, alpha * f.w);
    }
}

__global__ void elu_kernel(float* __restrict__ x, int total)
{
    int i = blockIdx.x * blockDim.x + threadIdx.x;
    if (i >= total) return;
    float v = x[i];
    x[i] = v > 0.f ? v : expm1f(v);
}

// ---------------------------------------------------------------------------
// launch
// ---------------------------------------------------------------------------
static inline int cdiv(long a, int b) { return (int)((a + b - 1) / b); }

extern "C" void kernel_launch(void* const* d_in, const int* in_sizes, int n_in,
                              void* d_out, int out_size)
{
    const float* x          = (const float*)d_in[0];
    const int*   edge_index = (const int*)d_in[1];
    const float* W1         = (const float*)d_in[2];
    const float* att_src1   = (const float*)d_in[3];
    const float* att_dst1   = (const float*)d_in[4];
    const float* b1         = (const float*)d_in[5];
    const float* W_mu       = (const float*)d_in[6];
    const float* att_src_mu = (const float*)d_in[7];
    const float* att_dst_mu = (const float*)d_in[8];
    const float* b_mu       = (const float*)d_in[9];
    const float* W_ls       = (const float*)d_in[10];
    const float* att_src_ls = (const float*)d_in[11];
    const float* att_dst_ls = (const float*)d_in[12];
    const float* b_ls       = (const float*)d_in[13];
    float* out = (float*)d_out;

    const int N  = in_sizes[0] / 128;   // 50000
    const int nE = in_sizes[1] / 2;     // 400000
    const int nTot = nE + N;            // edges + self-loops

    float *p_h1, *p_hact, *p_h2, *p_asrc, *p_adst, *p_den;
    unsigned* p_m;
    cudaGetSymbolAddress((void**)&p_h1,   g_h1);
    cudaGetSymbolAddress((void**)&p_hact, g_hact);
    cudaGetSymbolAddress((void**)&p_h2,   g_h2);
    cudaGetSymbolAddress((void**)&p_asrc, g_asrc);
    cudaGetSymbolAddress((void**)&p_adst, g_adst);
    cudaGetSymbolAddress((void**)&p_m,    g_m);
    cudaGetSymbolAddress((void**)&p_den,  g_den);

    const int T = 256;

    // ---- layer 1: h1 = x @ W1   [N,256]
    {
        dim3 grid(256 / BN, cdiv(N, BM));
        sgemm_k<<<grid, 256>>>(x, W1, p_h1, N, 128, 256, 256, 0);
    }
    att1_kernel<<<cdiv((long)N * 2, T), T>>>(p_h1, att_src1, att_dst1, p_asrc, p_adst, N);
    init_softmax_kernel<<<cdiv((long)N * 2, T), T>>>(p_m, p_den, N * 2);
    init_bias1_kernel<<<cdiv((long)N * 256, T), T>>>(p_hact, b1, N * 256);
    edge_max_kernel<<<cdiv((long)nTot * 2, T), T>>>(edge_index, nE, nTot, p_asrc, p_adst, p_m);
    edge_sum_kernel<<<cdiv((long)nTot * 2, T), T>>>(edge_index, nE, nTot, p_asrc, p_adst, p_m, p_den);
    edge_agg_kernel<128><<<cdiv((long)nTot * 2 * 32, T), T>>>(
        edge_index, nE, nTot, p_asrc, p_adst, p_m, p_den, p_h1, p_hact,
        /*nodeStride=*/256, /*headStride=*/128);
    elu_kernel<<<cdiv((long)N * 256, T), T>>>(p_hact, N * 256);

    // ---- layer 2: h2[:,0,:] = hact @ W_mu ; h2[:,1,:] = hact @ W_ls
    {
        dim3 grid(1, cdiv(N, BM));
        sgemm_k<<<grid, 256>>>(p_hact, W_mu, p_h2, N, 256, 64, 128, 0);
        sgemm_k<<<grid, 256>>>(p_hact, W_ls, p_h2, N, 256, 64, 128, 64);
    }
    att2_kernel<<<cdiv((long)N * 2, T), T>>>(p_h2, att_src_mu, att_dst_mu,
                                             att_src_ls, att_dst_ls, p_asrc, p_adst, N);
    init_softmax_kernel<<<cdiv((long)N * 2, T), T>>>(p_m, p_den, N * 2);
    init_bias2_kernel<<<cdiv((long)N * 128, T), T>>>(out, b_mu, b_ls, N);
    edge_max_kernel<<<cdiv((long)nTot * 2, T), T>>>(edge_index, nE, nTot, p_asrc, p_adst, p_m);
    edge_sum_kernel<<<cdiv((long)nTot * 2, T), T>>>(edge_index, nE, nTot, p_asrc, p_adst, p_m, p_den);
    edge_agg_kernel<64><<<cdiv((long)nTot * 2 * 32, T), T>>>(
        edge_index, nE, nTot, p_asrc, p_adst, p_m, p_den, p_h2, out,
        /*nodeStride=*/64, /*headStride=*/(long)N * 64);
}

// round 2
// speedup vs baseline: 1.6430x; 1.6430x over previous
#include <cuda_runtime.h>
#include <cuda_bf16.h>
#include <math.h>

#define MAX_N 50000
#define MAX_E 400000
#define MAX_ETOT (MAX_N + MAX_E)
#define NEG_SLOPE 0.2f

// ---------------- scratch (device globals, allocation-free) ----------------
__device__ float g_h1[MAX_N * 256];    // conv1 features  [N,2,128]
__device__ float g_hact[MAX_N * 256];  // ELU(aggregated) [N,256]
__device__ float g_h2[MAX_N * 128];    // layer2 feats    [N,{mu,ls},64]
__device__ float g_asrc[MAX_N * 2];
__device__ float g_adst[MAX_N * 2];
__device__ float g_b2[128];            // [b_mu | b_ls]
__device__ int   g_deg[MAX_N];
__device__ int   g_off[MAX_N + 1];
__device__ int   g_cur[MAX_N];
__device__ int   g_csr[MAX_ETOT];      // src node per CSR slot (sorted by dst)

// ---------------------------------------------------------------------------
// CSR build
// ---------------------------------------------------------------------------
__global__ void zero_deg_kernel(int* __restrict__ deg, int n)
{
    int i = blockIdx.x * blockDim.x + threadIdx.x;
    if (i < n) deg[i] = 0;
}

__global__ void hist_kernel(const int* __restrict__ ei, int nE, int nTot,
                            int* __restrict__ deg)
{
    int e = blockIdx.x * blockDim.x + threadIdx.x;
    if (e >= nTot) return;
    int d = (e < nE) ? ei[nE + e] : e - nE;
    atomicAdd(&deg[d], 1);
}

// single-block exclusive scan of deg -> off, cursor
__global__ __launch_bounds__(1024) void scan_kernel(
    const int* __restrict__ deg, int* __restrict__ off,
    int* __restrict__ cur, int N)
{
    __shared__ int ssum[1024];
    int tid = threadIdx.x;
    int chunk = (N + 1023) / 1024;
    int start = tid * chunk;
    int end = min(start + chunk, N);
    int s = 0;
    for (int i = start; i < end; i++) s += deg[i];
    ssum[tid] = s;
    __syncthreads();
    for (int o = 1; o < 1024; o <<= 1) {
        int v = 0;
        if (tid >= o) v = ssum[tid - o];
        __syncthreads();
        if (tid >= o) ssum[tid] += v;
        __syncthreads();
    }
    int base = (tid > 0) ? ssum[tid - 1] : 0;
    for (int i = start; i < end; i++) {
        off[i] = base;
        cur[i] = base;
        base += deg[i];
    }
    if (tid == 1023) off[N] = ssum[1023];
}

__global__ void scatter_kernel(const int* __restrict__ ei, int nE, int nTot,
                               int* __restrict__ cur, int* __restrict__ csr)
{
    int e = blockIdx.x * blockDim.x + threadIdx.x;
    if (e >= nTot) return;
    int s, d;
    if (e < nE) { s = ei[e]; d = ei[nE + e]; }
    else        { s = e - nE; d = s; }
    int pos = atomicAdd(&cur[d], 1);
    csr[pos] = s;
}

// ---------------------------------------------------------------------------
// SGEMM: 128x128 tile, BK=8, 256 threads, 8x8 microtile, float4 I/O
// ---------------------------------------------------------------------------
__global__ __launch_bounds__(256) void sgemm128_k(
    const float* __restrict__ A, const float* __restrict__ B,
    float* __restrict__ C, int M, int K, int ldb, int ldc)
{
    __shared__ float As[8][128];
    __shared__ float Bs[8][128];
    const int row0 = blockIdx.y * 128;
    const int col0 = blockIdx.x * 128;
    const int tid = threadIdx.x;
    const int am = tid >> 1, ak = (tid & 1) * 4;
    const int bk = tid >> 5, bc = (tid & 31) * 4;
    const int tr = (tid >> 4) << 3;
    const int tc = (tid & 15) << 3;

    float acc[8][8];
#pragma unroll
    for (int i = 0; i < 8; i++)
#pragma unroll
        for (int j = 0; j < 8; j++) acc[i][j] = 0.f;

    for (int k0 = 0; k0 < K; k0 += 8) {
        float4 av = make_float4(0.f, 0.f, 0.f, 0.f);
        if (row0 + am < M)
            av = *(const float4*)&A[(size_t)(row0 + am) * K + k0 + ak];
        As[ak + 0][am] = av.x;
        As[ak + 1][am] = av.y;
        As[ak + 2][am] = av.z;
        As[ak + 3][am] = av.w;
        float4 bv = *(const float4*)&B[(size_t)(k0 + bk) * ldb + col0 + bc];
        *(float4*)&Bs[bk][bc] = bv;
        __syncthreads();
#pragma unroll
        for (int k = 0; k < 8; k++) {
            float ra[8], rb[8];
            *(float4*)&ra[0] = *(float4*)&As[k][tr];
            *(float4*)&ra[4] = *(float4*)&As[k][tr + 4];
            *(float4*)&rb[0] = *(float4*)&Bs[k][tc];
            *(float4*)&rb[4] = *(float4*)&Bs[k][tc + 4];
#pragma unroll
            for (int i = 0; i < 8; i++)
#pragma unroll
                for (int j = 0; j < 8; j++) acc[i][j] += ra[i] * rb[j];
        }
        __syncthreads();
    }

#pragma unroll
    for (int i = 0; i < 8; i++) {
        int gr = row0 + tr + i;
        if (gr < M) {
            *(float4*)&C[(size_t)gr * ldc + col0 + tc]     = *(float4*)&acc[i][0];
            *(float4*)&C[(size_t)gr * ldc + col0 + tc + 4] = *(float4*)&acc[i][4];
        }
    }
}

// layer2 fused: cols 0..63 from W_mu, 64..127 from W_ls (both [K,64])
__global__ __launch_bounds__(256) void sgemm2_k(
    const float* __restrict__ A, const float* __restrict__ Bmu,
    const float* __restrict__ Bls, float* __restrict__ C, int M, int K)
{
    __shared__ float As[8][128];
    __shared__ float Bs[8][128];
    const int row0 = blockIdx.y * 128;
    const int tid = threadIdx.x;
    const int am = tid >> 1, ak = (tid & 1) * 4;
    const int bk = tid >> 5, bc = (tid & 31) * 4;
    const int tr = (tid >> 4) << 3;
    const int tc = (tid & 15) << 3;

    float acc[8][8];
#pragma unroll
    for (int i = 0; i < 8; i++)
#pragma unroll
        for (int j = 0; j < 8; j++) acc[i][j] = 0.f;

    for (int k0 = 0; k0 < K; k0 += 8) {
        float4 av = make_float4(0.f, 0.f, 0.f, 0.f);
        if (row0 + am < M)
            av = *(const float4*)&A[(size_t)(row0 + am) * K + k0 + ak];
        As[ak + 0][am] = av.x;
        As[ak + 1][am] = av.y;
        As[ak + 2][am] = av.z;
        As[ak + 3][am] = av.w;
        float4 bv;
        if (bc < 64) bv = *(const float4*)&Bmu[(size_t)(k0 + bk) * 64 + bc];
        else         bv = *(const float4*)&Bls[(size_t)(k0 + bk) * 64 + bc - 64];
        *(float4*)&Bs[bk][bc] = bv;
        __syncthreads();
#pragma unroll
        for (int k = 0; k < 8; k++) {
            float ra[8], rb[8];
            *(float4*)&ra[0] = *(float4*)&As[k][tr];
            *(float4*)&ra[4] = *(float4*)&As[k][tr + 4];
            *(float4*)&rb[0] = *(float4*)&Bs[k][tc];
            *(float4*)&rb[4] = *(float4*)&Bs[k][tc + 4];
#pragma unroll
            for (int i = 0; i < 8; i++)
#pragma unroll
                for (int j = 0; j < 8; j++) acc[i][j] += ra[i] * rb[j];
        }
        __syncthreads();
    }

#pragma unroll
    for (int i = 0; i < 8; i++) {
        int gr = row0 + tr + i;
        if (gr < M) {
            *(float4*)&C[(size_t)gr * 128 + tc]     = *(float4*)&acc[i][0];
            *(float4*)&C[(size_t)gr * 128 + tc + 4] = *(float4*)&acc[i][4];
        }
    }
}

// ---------------------------------------------------------------------------
// attention scalars
// ---------------------------------------------------------------------------
__global__ void att1_kernel(const float* __restrict__ h,
                            const float* __restrict__ att_src,
                            const float* __restrict__ att_dst,
                            float* __restrict__ asrc, float* __restrict__ adst,
                            int Nn)
{
    int i = blockIdx.x * blockDim.x + threadIdx.x;
    if (i >= Nn * 2) return;
    int n = i >> 1, hh = i & 1;
    const float* row = h + (size_t)n * 256 + hh * 128;
    const float* as = att_src + hh * 128;
    const float* ad = att_dst + hh * 128;
    float s = 0.f, d = 0.f;
#pragma unroll 8
    for (int c = 0; c < 128; c++) {
        float v = row[c];
        s += v * as[c];
        d += v * ad[c];
    }
    asrc[i] = s;
    adst[i] = d;
}

__global__ void att2_kernel(const float* __restrict__ h2,
                            const float* __restrict__ as_mu,
                            const float* __restrict__ ad_mu,
                            const float* __restrict__ as_ls,
                            const float* __restrict__ ad_ls,
                            float* __restrict__ asrc, float* __restrict__ adst,
                            int Nn)
{
    int i = blockIdx.x * blockDim.x + threadIdx.x;
    if (i >= Nn * 2) return;
    int n = i >> 1, hh = i & 1;
    const float* row = h2 + (size_t)n * 128 + hh * 64;
    const float* as = hh ? as_ls : as_mu;
    const float* ad = hh ? ad_ls : ad_mu;
    float s = 0.f, d = 0.f;
#pragma unroll 8
    for (int c = 0; c < 64; c++) {
        float v = row[c];
        s += v * as[c];
        d += v * ad[c];
    }
    asrc[i] = s;
    adst[i] = d;
}

__global__ void copy_b2_kernel(const float* __restrict__ b_mu,
                               const float* __restrict__ b_ls,
                               float* __restrict__ b2)
{
    int i = threadIdx.x;
    if (i < 64)       b2[i] = b_mu[i];
    else if (i < 128) b2[i] = b_ls[i - 64];
}

// ---------------------------------------------------------------------------
// fused softmax + aggregation: one warp per (node, head), no atomics
// ---------------------------------------------------------------------------
template <int C, bool DOELU>
__global__ void agg_kernel(const int* __restrict__ off, const int* __restrict__ csr,
                           const float* __restrict__ asrc, const float* __restrict__ adst,
                           const float* __restrict__ feat, const float* __restrict__ bias,
                           float* __restrict__ out, long outNode, long outHead, int Nn)
{
    int warp = (blockIdx.x * blockDim.x + threadIdx.x) >> 5;
    int lane = threadIdx.x & 31;
    if (warp >= Nn * 2) return;
    int n = warp >> 1, h = warp & 1;
    int o0 = off[n], o1 = off[n + 1];
    float ad = adst[n * 2 + h];

    // pass 1: max
    float m = -INFINITY;
    for (int j = o0 + lane; j < o1; j += 32) {
        float e = asrc[csr[j] * 2 + h] + ad;
        e = e > 0.f ? e : NEG_SLOPE * e;
        m = fmaxf(m, e);
    }
#pragma unroll
    for (int o = 16; o; o >>= 1) m = fmaxf(m, __shfl_xor_sync(~0u, m, o));

    // pass 2: denom
    float den = 0.f;
    for (int j = o0 + lane; j < o1; j += 32) {
        float e = asrc[csr[j] * 2 + h] + ad;
        e = e > 0.f ? e : NEG_SLOPE * e;
        den += __expf(e - m);
    }
#pragma unroll
    for (int o = 16; o; o >>= 1) den += __shfl_xor_sync(~0u, den, o);
    float inv = 1.f / (den + 1e-16f);

    // pass 3: weighted gather-accumulate (each lane owns a float4 chunk)
    constexpr int NV = C / 4;
    float4 acc = make_float4(0.f, 0.f, 0.f, 0.f);
    for (int j = o0; j < o1; j++) {
        int s = csr[j];
        float e = asrc[s * 2 + h] + ad;
        e = e > 0.f ? e : NEG_SLOPE * e;
        float alpha = __expf(e - m) * inv;
        if (lane < NV) {
            float4 f = *((const float4*)(feat + (size_t)s * 2 * C + h * C) + lane);
            acc.x += alpha * f.x;
            acc.y += alpha * f.y;
            acc.z += alpha * f.z;
            acc.w += alpha * f.w;
        }
    }
    if (lane < NV) {
        float4 b4 = *((const float4*)(bias + h * C) + lane);
        acc.x += b4.x; acc.y += b4.y; acc.z += b4.z; acc.w += b4.w;
        if (DOELU) {
            acc.x = acc.x > 0.f ? acc.x : expm1f(acc.x);
            acc.y = acc.y > 0.f ? acc.y : expm1f(acc.y);
            acc.z = acc.z > 0.f ? acc.z : expm1f(acc.z);
            acc.w = acc.w > 0.f ? acc.w : expm1f(acc.w);
        }
        *((float4*)(out + (size_t)n * outNode + (size_t)h * outHead) + lane) = acc;
    }
}

// ---------------------------------------------------------------------------
static inline int cdiv(long a, int b) { return (int)((a + b - 1) / b); }

extern "C" void kernel_launch(void* const* d_in, const int* in_sizes, int n_in,
                              void* d_out, int out_size)
{
    const float* x          = (const float*)d_in[0];
    const int*   edge_index = (const int*)d_in[1];
    const float* W1         = (const float*)d_in[2];
    const float* att_src1   = (const float*)d_in[3];
    const float* att_dst1   = (const float*)d_in[4];
    const float* b1         = (const float*)d_in[5];
    const float* W_mu       = (const float*)d_in[6];
    const float* att_src_mu = (const float*)d_in[7];
    const float* att_dst_mu = (const float*)d_in[8];
    const float* b_mu       = (const float*)d_in[9];
    const float* W_ls       = (const float*)d_in[10];
    const float* att_src_ls = (const float*)d_in[11];
    const float* att_dst_ls = (const float*)d_in[12];
    const float* b_ls       = (const float*)d_in[13];
    float* out = (float*)d_out;

    const int N  = in_sizes[0] / 128;
    const int nE = in_sizes[1] / 2;
    const int nTot = nE + N;

    float *p_h1, *p_hact, *p_h2, *p_asrc, *p_adst, *p_b2;
    int *p_deg, *p_off, *p_cur, *p_csr;
    cudaGetSymbolAddress((void**)&p_h1,   g_h1);
    cudaGetSymbolAddress((void**)&p_hact, g_hact);
    cudaGetSymbolAddress((void**)&p_h2,   g_h2);
    cudaGetSymbolAddress((void**)&p_asrc, g_asrc);
    cudaGetSymbolAddress((void**)&p_adst, g_adst);
    cudaGetSymbolAddress((void**)&p_b2,   g_b2);
    cudaGetSymbolAddress((void**)&p_deg,  g_deg);
    cudaGetSymbolAddress((void**)&p_off,  g_off);
    cudaGetSymbolAddress((void**)&p_cur,  g_cur);
    cudaGetSymbolAddress((void**)&p_csr,  g_csr);

    const int T = 256;

    // ---- CSR build (dst-sorted incoming edges, self-loops appended)
    zero_deg_kernel<<<cdiv(N, T), T>>>(p_deg, N);
    hist_kernel<<<cdiv(nTot, T), T>>>(edge_index, nE, nTot, p_deg);
    scan_kernel<<<1, 1024>>>(p_deg, p_off, p_cur, N);
    scatter_kernel<<<cdiv(nTot, T), T>>>(edge_index, nE, nTot, p_cur, p_csr);

    // ---- layer 1
    {
        dim3 grid(2, cdiv(N, 128));
        sgemm128_k<<<grid, 256>>>(x, W1, p_h1, N, 128, 256, 256);
    }
    att1_kernel<<<cdiv((long)N * 2, T), T>>>(p_h1, att_src1, att_dst1, p_asrc, p_adst, N);
    agg_kernel<128, true><<<cdiv((long)N * 2 * 32, T), T>>>(
        p_off, p_csr, p_asrc, p_adst, p_h1, b1, p_hact, 256, 128, N);

    // ---- layer 2 (mu & logstd fused as 2 heads)
    {
        dim3 grid(1, cdiv(N, 128));
        sgemm2_k<<<grid, 256>>>(p_hact, W_mu, W_ls, p_h2, N, 256);
    }
    copy_b2_kernel<<<1, 128>>>(b_mu, b_ls, p_b2);
    att2_kernel<<<cdiv((long)N * 2, T), T>>>(p_h2, att_src_mu, att_dst_mu,
                                             att_src_ls, att_dst_ls, p_asrc, p_adst, N);
    agg_kernel<64, false><<<cdiv((long)N * 2 * 32, T), T>>>(
        p_off, p_csr, p_asrc, p_adst, p_h2, p_b2, out, 64, (long)N * 64, N);
}